// round 16
// baseline (speedup 1.0000x reference)
#include <cuda_runtime.h>
#include <cuda_bf16.h>
#include <cuda_fp16.h>
#include <math.h>

// StatEncoder — persistent mma.sync fp16 GRU, plain sm_100 target.
//   R16 = R15 with the prep bias-table bug fixed (the N_B4 branch wrote 4
//   entries per thread over 1024 indices -> clobbered cbz/bhn/bin + OOB).
//   Architecture: zero inter-CTA comm; CTA owns 16 rows x all 768 cols; h in
//   SMEM; one __syncthreads/step; MUFU.TANH gates; x@Wih_{r,z} + biases
//   folded into MMA accumulator INIT (d = A*B + d). 96 HMMA/warp/step.
//   16 h-chunks: 7 SMEM-resident, 9 streamed via depth-4 register ring.

#define Bsz   2048
#define Wlen  128
#define Fin   8
#define Hdim  256
#define THREADS 512

#define N_WF   98304           // 8c x 16q x 12nf x 64 words
#define N_WX3  6144            // 8c x 32jl x 3g x 8  (Wih r/z/n, fp32)
#define N_B4   1024            // cbr | cbz | bhn | bin
#define N_WPT  131072

// dynamic smem layout (32-bit words)
#define SW_RES 0               // resident B frags: [c(8)][slot(7)][768]
#define SW_H   43008           // h A-buffer: [par(2)][chunk(16)][128]
#define SW_WX  47104           // 6144 floats (Wih r/z/n per j)
#define SW_BIAS 53248          // 1024 floats
#define SW_XB  54272           // x stage: [par(2)][row(16)][8] floats
#define SM_WORDS 54528
#define SM_TOTAL (SM_WORDS * 4)   // 218,112 B

// ---- static device scratch ----
__device__ __align__(256) unsigned g_wfrag[N_WF];
__device__ __align__(256) float    g_wx3[N_WX3];
__device__ __align__(256) float    g_b4[N_B4];
__device__ __align__(256) float    g_hfinal[Bsz * Hdim];
__device__ __align__(256) float    g_Wpt[N_WPT];

// ---- helpers ----
static __device__ __forceinline__ unsigned f2h2(float a, float b) {
    return (unsigned)__half_as_ushort(__float2half_rn(a)) |
           ((unsigned)__half_as_ushort(__float2half_rn(b)) << 16);
}
static __device__ __forceinline__ float tanh_fast(float v) {
    float y;
    asm("tanh.approx.f32 %0, %1;" : "=f"(y) : "f"(v));
    return y;
}

#define MMAH(d, a, b0v, b1v)                                                   \
    asm volatile(                                                              \
        "mma.sync.aligned.m16n8k16.row.col.f32.f16.f16.f32 "                   \
        "{%0,%1,%2,%3}, {%4,%5,%6,%7}, {%8,%9}, {%0,%1,%2,%3};"                \
        : "+f"(d[0]), "+f"(d[1]), "+f"(d[2]), "+f"(d[3])                       \
        : "r"(a.x), "r"(a.y), "r"(a.z), "r"(a.w), "r"(b0v), "r"(b1v))

// ---------------- prep ------------------------------------------------------
#define N_PREP (N_WF + N_WX3 + N_B4 + N_WPT)

__global__ void prep_kernel(const float* __restrict__ Whh_f,
                            const float* __restrict__ Wih_f,
                            const float* __restrict__ bih_f,
                            const float* __restrict__ bhh_f,
                            const float* __restrict__ Wp) {
    int idx = blockIdx.x * blockDim.x + threadIdx.x;
    if (idx < N_WF) {
        int c  = idx / 12288, r = idx % 12288;
        int q  = r / 768,     r3 = r % 768;
        int nfg = r3 / 64,    r4 = r3 % 64;
        int L  = r4 >> 1,     ws = r4 & 1;
        int n  = nfg * 8 + (L >> 2);
        int wc = n / 48, r5 = n % 48;
        int gate = r5 / 16;                 // 0=r, 1=z, 2=hn
        int jl = wc * 16 + (r5 % 16);
        int j  = c * 32 + jl;
        int k0 = q * 16 + ((L & 3) << 1) + ws * 8;
        float v0 = Whh_f[(gate * 256 + j) * 256 + k0];
        float v1 = Whh_f[(gate * 256 + j) * 256 + k0 + 1];
        g_wfrag[idx] = f2h2(v0, v1);
    } else if (idx < N_WF + N_WX3) {
        int i = idx - N_WF;
        int c = i / 768, r = i % 768;
        int jl = r / 24, g = (r % 24) / 8, e = r % 8;
        int j = c * 32 + jl;
        g_wx3[i] = Wih_f[(g * 256 + j) * 8 + e];    // g: 0=r, 1=z, 2=n
    } else if (idx < N_WF + N_WX3 + N_B4) {
        // FIXED: one entry per thread, in-bounds by construction
        int i = idx - N_WF - N_WX3;       // 0..1023
        int g = i >> 8, j = i & 255;
        float v;
        if (g == 0)      v = bih_f[j] + bhh_f[j];               // cbr
        else if (g == 1) v = bih_f[256 + j] + bhh_f[256 + j];   // cbz
        else if (g == 2) v = bhh_f[512 + j];                    // bhn
        else             v = bih_f[512 + j];                    // bin
        g_b4[i] = v;
    } else if (idx < N_PREP) {
        int i = idx - N_WF - N_WX3 - N_B4;
        int m = i / Hdim, j = i - m * Hdim;
        g_Wpt[i] = Wp[j * (2 * Hdim) + m];
    }
}

// ---------------- persistent GRU (no inter-CTA sync) ------------------------
__global__ void __launch_bounds__(THREADS, 1)
gru_persist(const float* __restrict__ x) {
    extern __shared__ unsigned smem[];
    const int tid  = threadIdx.x;
    const int bcta = blockIdx.x;        // rows 16*bcta .. 16*bcta+15

    // resident weights: slots 0..6 = h-chunks 0..6
    for (int i = tid; i < 43008; i += THREADS) {
        int cc = i / 5376, r = i % 5376;
        smem[SW_RES + i] = g_wfrag[cc * 12288 + r];
    }
    for (int i = tid; i < 6144; i += THREADS)
        ((float*)(smem + SW_WX))[i] = g_wx3[i];
    for (int i = tid; i < 1024; i += THREADS)
        ((float*)(smem + SW_BIAS))[i] = g_b4[i];
    for (int i = tid; i < 2048; i += THREADS)
        smem[SW_H + i] = 0u;            // parity-0 h = h(0) = 0
    // stage x(0) into xbuf[0] (warp 0)
    if (tid < 32) {
        const int prow = tid >> 1, phalf = tid & 1;
        float4 v = __ldg((const float4*)(x + (size_t)(bcta * 16 + prow) * (Wlen * Fin) + phalf * 4));
        *(float4*)((float*)(smem + SW_XB) + prow * 8 + phalf * 4) = v;
    }
    __syncthreads();

    const int w  = tid >> 5, L = tid & 31;
    const int c  = w >> 1;              // column group 0..7
    const int wc = w & 1;               // half (16 jl)
    const float* swx  = (const float*)(smem + SW_WX);
    const float* sb   = (const float*)(smem + SW_BIAS);
    const int resbase = c * 5376 + wc * 384;          // + slot*768 + nf*64 + 2L
    const unsigned* gW = g_wfrag + c * 12288 + wc * 384;

    float hold[8];
#pragma unroll
    for (int i = 0; i < 8; i++) hold[i] = 0.0f;

    for (int t = 0; t < Wlen; t++) {
        const int par = t & 1;
        const unsigned* hsrc = smem + SW_H + par * 2048;
        unsigned* hdst = smem + SW_H + (par ^ 1) * 2048;
        __syncthreads();    // h(t) + x(t) staged; old hdst/xbuf reads done

        // x(t) rows for this lane (LDS, staged last step)
        const float* xb = (const float*)(smem + SW_XB) + par * 128;
        float x80[8], x81[8];
        {
            const float* xr0 = xb + (L >> 2) * 8;
            const float* xr1 = xb + ((L >> 2) + 8) * 8;
#pragma unroll
            for (int u = 0; u < 8; u++) { x80[u] = xr0[u]; x81[u] = xr1[u]; }
        }

        // warp 0: prefetch x(t+1) (covered by the whole MMA phase)
        float4 xnv = make_float4(0.f, 0.f, 0.f, 0.f);
        const bool pf = (tid < 32) && (t < Wlen - 1);
        if (pf) {
            const int prow = tid >> 1, phalf = tid & 1;
            xnv = __ldg((const float4*)(x + (size_t)(bcta * 16 + prow) * (Wlen * Fin)
                                          + (t + 1) * Fin + phalf * 4));
        }

        // issue ALL 4 initial streamed-B loads (chunks 7..10) up front
        uint2 Bs[4][6];
#pragma unroll
        for (int d = 0; d < 4; d++)
#pragma unroll
            for (int nf = 0; nf < 6; nf++)
                Bs[d][nf] = __ldcg((const uint2*)(gW + (7 + d) * 768 + nf * 64 + (L << 1)));

        // ---- acc INIT = x@Wih_{r,z} + biases (fp32, folds the old x-chunk)
        float acc[6][4];
#pragma unroll
        for (int fp = 0; fp < 2; fp++) {
#pragma unroll
            for (int e = 0; e < 2; e++) {
                const int jl = wc * 16 + 2 * (L & 3) + 8 * fp + e;
                const int j  = c * 32 + jl;
                const float* wj = swx + j * 24;
                float r0 = sb[j], r1 = sb[j];             // cbr
                float z0 = sb[256 + j], z1 = sb[256 + j]; // cbz
#pragma unroll
                for (int u = 0; u < 8; u++) {
                    r0 = fmaf(x80[u], wj[u], r0);
                    r1 = fmaf(x81[u], wj[u], r1);
                    z0 = fmaf(x80[u], wj[8 + u], z0);
                    z1 = fmaf(x81[u], wj[8 + u], z1);
                }
                acc[fp][e]         = r0;  acc[fp][2 + e]     = r1;
                acc[2 + fp][e]     = z0;  acc[2 + fp][2 + e] = z1;
                const float bhn = sb[512 + j];
                acc[4 + fp][e]     = bhn; acc[4 + fp][2 + e] = bhn;
            }
        }

        // resident h-chunks 0..6 (A from SMEM, B from SMEM)
#pragma unroll
        for (int q = 0; q < 7; q++) {
            uint4 af = *(const uint4*)(hsrc + q * 128 + (L << 2));
            const unsigned* bb = smem + resbase + q * 768 + (L << 1);
#pragma unroll
            for (int nf = 0; nf < 6; nf++) {
                uint2 bw = *(const uint2*)(bb + nf * 64);
                MMAH(acc[nf], af, bw.x, bw.y);
            }
        }
        // streamed h-chunks 7..15 (A from SMEM, B from depth-4 register ring)
#pragma unroll
        for (int d = 0; d < 9; d++) {
            const int q = 7 + d;
            const int s = d & 3;
            uint4 af = *(const uint4*)(hsrc + q * 128 + (L << 2));
#pragma unroll
            for (int nf = 0; nf < 6; nf++)
                MMAH(acc[nf], af, Bs[s][nf].x, Bs[s][nf].y);
            if (d + 4 < 9) {
#pragma unroll
                for (int nf = 0; nf < 6; nf++)
                    Bs[s][nf] = __ldcg((const uint2*)(gW + (q + 4) * 768 + nf * 64 + (L << 1)));
            }
        }

        // stage x(t+1) into the other xbuf (ordered by next step's sync)
        if (pf) {
            const int prow = tid >> 1, phalf = tid & 1;
            *(float4*)((float*)(smem + SW_XB) + (par ^ 1) * 128 + prow * 8 + phalf * 4) = xnv;
        }

        // ---- epilogue: inn (fp32) + MUFU.TANH gates + h update + STS ------
        float hv[2][2][2];                 // [rh][fp][e]
#pragma unroll
        for (int fp = 0; fp < 2; fp++) {
#pragma unroll
            for (int e = 0; e < 2; e++) {
                const int jl = wc * 16 + 2 * (L & 3) + 8 * fp + e;
                const int j  = c * 32 + jl;
                const float* wn = swx + j * 24 + 16;
                float xn0 = sb[768 + j], xn1 = sb[768 + j];   // bin
#pragma unroll
                for (int u = 0; u < 8; u++) {
                    xn0 = fmaf(x80[u], wn[u], xn0);
                    xn1 = fmaf(x81[u], wn[u], xn1);
                }
#pragma unroll
                for (int rh = 0; rh < 2; rh++) {
                    const int ci = rh * 2 + e;
                    float rp  = acc[fp][ci];          // bias+x already inside
                    float zp  = acc[2 + fp][ci];
                    float hnv = acc[4 + fp][ci];      // includes bhn
                    float r = fmaf(tanh_fast(0.5f * rp), 0.5f, 0.5f);
                    float z = fmaf(tanh_fast(0.5f * zp), 0.5f, 0.5f);
                    float an = fmaf(r, hnv, (rh ? xn1 : xn0));
                    float n  = tanh_fast(an);
                    const int hidx = (rh * 2 + fp) * 2 + e;
                    float h = fmaf(z, hold[hidx] - n, n);   // (1-z)n + z*hold
                    hold[hidx] = h;
                    hv[rh][fp][e] = h;
                }
            }
        }
        unsigned whi[4];
#pragma unroll
        for (int rh = 0; rh < 2; rh++)
#pragma unroll
            for (int fp = 0; fp < 2; fp++)
                whi[rh + 2 * fp] = f2h2(hv[rh][fp][0], hv[rh][fp][1]);
        // warp w produces exactly chunk w
        *(uint4*)(hdst + w * 128 + (L << 2)) =
            make_uint4(whi[0], whi[1], whi[2], whi[3]);
    }

    // final h -> plain layout for the head
#pragma unroll
    for (int rh = 0; rh < 2; rh++) {
        const int row = bcta * 16 + (L >> 2) + 8 * rh;
#pragma unroll
        for (int fp = 0; fp < 2; fp++)
#pragma unroll
            for (int e = 0; e < 2; e++) {
                const int jl = wc * 16 + 2 * (L & 3) + 8 * fp + e;
                const int hidx = (rh * 2 + fp) * 2 + e;
                g_hfinal[(size_t)row * 256 + c * 32 + jl] = hold[hidx];
            }
    }
}

// ---------------- head: h_bwd + projection + GELU + LayerNorm ---------------
__global__ void __launch_bounds__(256)
head_kernel(const float* __restrict__ x,
            const float* __restrict__ Wih_b,
            const float* __restrict__ bih_b,
            const float* __restrict__ bhh_b,
            const float* __restrict__ bp,
            const float* __restrict__ gamma,
            const float* __restrict__ beta,
            float* __restrict__ out) {
    __shared__ float hf[8][Hdim];
    __shared__ float hb[8][Hdim];
    __shared__ float ys[8][Hdim];
    __shared__ float xs[8][Fin];

    const int tx = threadIdx.x;
    const int b0 = blockIdx.x * 8;

    for (int idx = tx; idx < 8 * Hdim; idx += 256) {
        int r = idx >> 8, k = idx & 255;
        hf[r][k] = g_hfinal[(size_t)(b0 + r) * Hdim + k];
    }
    if (tx < 64) {
        int r = tx >> 3, cc = tx & 7;
        xs[r][cc] = x[(size_t)(b0 + r) * (Wlen * Fin) + (Wlen - 1) * Fin + cc];
    }
    __syncthreads();

    {   // backward cell at h0 = 0 (exact math)
        const int j = tx;
        float wr[Fin], wz[Fin], wn[Fin];
#pragma unroll
        for (int cc = 0; cc < Fin; cc++) {
            wr[cc] = Wih_b[j * Fin + cc];
            wz[cc] = Wih_b[(256 + j) * Fin + cc];
            wn[cc] = Wih_b[(512 + j) * Fin + cc];
        }
        const float bir = bih_b[j],       bhr = bhh_b[j];
        const float biz = bih_b[256 + j], bhz = bhh_b[256 + j];
        const float bin = bih_b[512 + j], bhn = bhh_b[512 + j];
#pragma unroll
        for (int r8 = 0; r8 < 8; r8++) {
            float gr = bir + bhr, gz = biz + bhz, gn = bin;
#pragma unroll
            for (int cc = 0; cc < Fin; cc++) {
                float xvv = xs[r8][cc];
                gr = fmaf(xvv, wr[cc], gr);
                gz = fmaf(xvv, wz[cc], gz);
                gn = fmaf(xvv, wn[cc], gn);
            }
            float r = 1.0f / (1.0f + __expf(-gr));
            float z = 1.0f / (1.0f + __expf(-gz));
            float an = gn + r * bhn;
            an = fminf(fmaxf(an, -15.0f), 15.0f);
            float e = __expf(-2.0f * an);
            float n = (1.0f - e) / (1.0f + e);
            hb[r8][j] = (1.0f - z) * n;
        }
    }
    __syncthreads();

    {   // projection + exact GELU
        const int j = tx;
#pragma unroll
        for (int r8 = 0; r8 < 8; r8++) {
            float acc = bp[j];
#pragma unroll 4
            for (int k = 0; k < Hdim; k++)
                acc = fmaf(hf[r8][k], g_Wpt[k * Hdim + j], acc);
#pragma unroll 4
            for (int k = 0; k < Hdim; k++)
                acc = fmaf(hb[r8][k], g_Wpt[(Hdim + k) * Hdim + j], acc);
            ys[r8][j] = 0.5f * acc * (1.0f + erff(acc * 0.70710678118654752f));
        }
    }
    __syncthreads();

    const int w = tx >> 5, l = tx & 31;
    float s1 = 0.f, s2 = 0.f;
#pragma unroll
    for (int m = 0; m < 8; m++) {
        float v = ys[w][l + 32 * m];
        s1 += v; s2 += v * v;
    }
#pragma unroll
    for (int o = 16; o > 0; o >>= 1) {
        s1 += __shfl_xor_sync(0xffffffffu, s1, o);
        s2 += __shfl_xor_sync(0xffffffffu, s2, o);
    }
    const float mu  = s1 * (1.0f / 256.0f);
    const float var = s2 * (1.0f / 256.0f) - mu * mu;
    const float inv = rsqrtf(var + 1e-5f);
#pragma unroll
    for (int m = 0; m < 8; m++) {
        int col = l + 32 * m;
        float v = (ys[w][col] - mu) * inv;
        out[(size_t)(b0 + w) * Hdim + col] = v * gamma[col] + beta[col];
    }
}

// ---------------------------------------------------------------------------
extern "C" void kernel_launch(void* const* d_in, const int* in_sizes, int n_in,
                              void* d_out, int out_size) {
    const float* x     = (const float*)d_in[0];
    const float* Wih_f = (const float*)d_in[1];
    const float* Whh_f = (const float*)d_in[2];
    const float* bih_f = (const float*)d_in[3];
    const float* bhh_f = (const float*)d_in[4];
    const float* Wih_b = (const float*)d_in[5];
    /* Whh_b = d_in[6] unused: backward cell has h0 = 0 */
    const float* bih_b = (const float*)d_in[7];
    const float* bhh_b = (const float*)d_in[8];
    const float* Wp    = (const float*)d_in[9];
    const float* bp    = (const float*)d_in[10];
    const float* gamma = (const float*)d_in[11];
    const float* beta  = (const float*)d_in[12];
    float* out = (float*)d_out;

    cudaFuncSetAttribute(gru_persist, cudaFuncAttributeMaxDynamicSharedMemorySize, SM_TOTAL);

    prep_kernel<<<(N_PREP + 255) / 256, 256>>>(Whh_f, Wih_f, bih_f, bhh_f, Wp);
    gru_persist<<<Bsz / 16, THREADS, SM_TOTAL>>>(x);
    head_kernel<<<Bsz / 8, 256>>>(x, Wih_b, bih_b, bhh_b, bp, gamma, beta, out);
}

// round 17
// speedup vs baseline: 1.2246x; 1.2246x over previous
#include <cuda_runtime.h>
#include <cuda_bf16.h>
#include <cuda_fp16.h>
#include <math.h>

// StatEncoder — persistent mma.sync fp16 GRU, plain sm_100 target.
//   R17 = R14 (champion, 721us) + inn gate folded into the tensor pipe:
//   a 2-MMA "inn-xfold" (A = xfrag with const-1 at k8 carrying bin,
//   B = Wih_n rows) into a separate accumulator acc_inn that h-chunks never
//   touch. Removes the epilogue's 16-FMA inn chain + LDS tables entirely.
//   Everything else identical to R14: zero inter-CTA comm; CTA owns 16 rows
//   x all 768 cols; h in SMEM; one __syncthreads/step; MUFU.TANH gates;
//   7 resident h-chunks + 9 streamed via depth-4 register ring; x staged.

#define Bsz   2048
#define Wlen  128
#define Fin   8
#define Hdim  256
#define THREADS 512

#define N_WF   104448          // 8c x 17q x 12nf x 64 words (16 h + xfold)
#define N_WFX  2048            // inn-xfold frags: [c(8)][wc(2)][nfi(2)][64]
#define N_WPT  131072

// dynamic smem layout (32-bit words)
#define SW_RES 0               // resident B frags: [c(8)][slot(8)][768]
#define SW_FX  49152           // inn-xfold B frags (2048 words)
#define SW_H   51200           // h A-buffer: [par(2)][chunk(16)][128]
#define SW_XB  55296           // x stage: [par(2)][row(16)][8] floats
#define SM_WORDS 55552
#define SM_TOTAL (SM_WORDS * 4)   // 222,208 B

// ---- static device scratch ----
__device__ __align__(256) unsigned g_wfrag[N_WF];
__device__ __align__(256) unsigned g_wfx[N_WFX];
__device__ __align__(256) float    g_hfinal[Bsz * Hdim];
__device__ __align__(256) float    g_Wpt[N_WPT];

// ---- helpers ----
static __device__ __forceinline__ unsigned f2h2(float a, float b) {
    return (unsigned)__half_as_ushort(__float2half_rn(a)) |
           ((unsigned)__half_as_ushort(__float2half_rn(b)) << 16);
}
static __device__ __forceinline__ float tanh_fast(float v) {
    float y;
    asm("tanh.approx.f32 %0, %1;" : "=f"(y) : "f"(v));
    return y;
}

#define MMAH(d, a, b0v, b1v)                                                   \
    asm volatile(                                                              \
        "mma.sync.aligned.m16n8k16.row.col.f32.f16.f16.f32 "                   \
        "{%0,%1,%2,%3}, {%4,%5,%6,%7}, {%8,%9}, {%0,%1,%2,%3};"                \
        : "+f"(d[0]), "+f"(d[1]), "+f"(d[2]), "+f"(d[3])                       \
        : "r"(a.x), "r"(a.y), "r"(a.z), "r"(a.w), "r"(b0v), "r"(b1v))

// ---------------- prep ------------------------------------------------------
#define N_PREP (N_WF + N_WFX + N_WPT)

__global__ void prep_kernel(const float* __restrict__ Whh_f,
                            const float* __restrict__ Wih_f,
                            const float* __restrict__ bih_f,
                            const float* __restrict__ bhh_f,
                            const float* __restrict__ Wp) {
    int idx = blockIdx.x * blockDim.x + threadIdx.x;
    if (idx < N_WF) {
        int c  = idx / 13056, r = idx % 13056;
        int q  = r / 768,     r3 = r % 768;
        int nfg = r3 / 64,    r4 = r3 % 64;
        int L  = r4 >> 1,     ws = r4 & 1;
        int n  = nfg * 8 + (L >> 2);
        int wc = n / 48, r5 = n % 48;
        int gate = r5 / 16;                 // 0=r, 1=z, 2=hn
        int jl = wc * 16 + (r5 % 16);
        int j  = c * 32 + jl;
        float v0, v1;
        if (q < 16) {
            int k0 = q * 16 + ((L & 3) << 1) + ws * 8;
            v0 = Whh_f[(gate * 256 + j) * 256 + k0];
            v1 = Whh_f[(gate * 256 + j) * 256 + k0 + 1];
        } else {
            // xfold chunk: k0..7 = Wih (r,z), k8 = combined bias, else 0
            int kb = ((L & 3) << 1) + ws * 8;
            float e[2];
#pragma unroll
            for (int u = 0; u < 2; u++) {
                int kk = kb + u;
                float v = 0.0f;
                if (kk < 8) {
                    if (gate < 2) v = Wih_f[(gate * 256 + j) * 8 + kk];
                } else if (kk == 8) {
                    if (gate == 0)      v = bih_f[j] + bhh_f[j];
                    else if (gate == 1) v = bih_f[256 + j] + bhh_f[256 + j];
                    else                v = bhh_f[512 + j];
                }
                e[u] = v;
            }
            v0 = e[0]; v1 = e[1];
        }
        g_wfrag[idx] = f2h2(v0, v1);
    } else if (idx < N_WF + N_WFX) {
        // inn-xfold frags: k0..7 = Wih_n, k8 = bin, else 0
        int i = idx - N_WF;
        int c = i / 256, r = i % 256;
        int wc = r / 128, r2 = r % 128;
        int nfi = r2 / 64, r3 = r2 % 64;
        int L = r3 >> 1, ws = r3 & 1;
        int n = L >> 2;                    // B col within the 8-wide tile
        int jl = wc * 16 + nfi * 8 + n;
        int j = c * 32 + jl;
        int kb = ((L & 3) << 1) + ws * 8;
        float e[2];
#pragma unroll
        for (int u = 0; u < 2; u++) {
            int kk = kb + u;
            float v = 0.0f;
            if (kk < 8)       v = Wih_f[(512 + j) * 8 + kk];
            else if (kk == 8) v = bih_f[512 + j];
            e[u] = v;
        }
        g_wfx[i] = f2h2(e[0], e[1]);
    } else if (idx < N_PREP) {
        int i = idx - N_WF - N_WFX;
        int m = i / Hdim, j = i - m * Hdim;
        g_Wpt[i] = Wp[j * (2 * Hdim) + m];
    }
}

// ---------------- persistent GRU (no inter-CTA sync) ------------------------
__global__ void __launch_bounds__(THREADS, 1)
gru_persist(const float* __restrict__ x) {
    extern __shared__ unsigned smem[];
    const int tid  = threadIdx.x;
    const int bcta = blockIdx.x;        // rows 16*bcta .. 16*bcta+15

    // resident weights: slots 0..6 = h-chunks 0..6, slot 7 = xfold chunk 16
    for (int i = tid; i < 49152; i += THREADS) {
        int cc = i / 6144, r = i % 6144;
        int s = r / 768, off = r - s * 768;
        int q = (s < 7) ? s : 16;
        smem[SW_RES + i] = g_wfrag[cc * 13056 + q * 768 + off];
    }
    for (int i = tid; i < 2048; i += THREADS)
        smem[SW_FX + i] = g_wfx[i];
    for (int i = tid; i < 4096; i += THREADS)
        smem[SW_H + i] = 0u;            // both parities zeroed; par0 = h(0)=0
    // stage x(0) into xbuf[0] (warp 0)
    if (tid < 32) {
        const int prow = tid >> 1, phalf = tid & 1;
        float4 v = __ldg((const float4*)(x + (size_t)(bcta * 16 + prow) * (Wlen * Fin) + phalf * 4));
        *(float4*)((float*)(smem + SW_XB) + prow * 8 + phalf * 4) = v;
    }
    __syncthreads();

    const int w  = tid >> 5, L = tid & 31;
    const int c  = w >> 1;              // column group 0..7
    const int wc = w & 1;               // half (16 jl)
    const int resbase = c * 6144 + wc * 384;          // + slot*768 + nf*64 + 2L
    const int fxbase  = SW_FX + c * 256 + wc * 128 + (L << 1);
    const unsigned* gW = g_wfrag + c * 13056 + wc * 384;

    float hold[8];
#pragma unroll
    for (int i = 0; i < 8; i++) hold[i] = 0.0f;

    for (int t = 0; t < Wlen; t++) {
        const int par = t & 1;
        const unsigned* hsrc = smem + SW_H + par * 2048;
        unsigned* hdst = smem + SW_H + (par ^ 1) * 2048;
        __syncthreads();    // h(t) + x(t) staged; old hdst/xbuf reads done

        float acc[6][4];
#pragma unroll
        for (int nf = 0; nf < 6; nf++)
#pragma unroll
            for (int u = 0; u < 4; u++) acc[nf][u] = 0.0f;
        float acc_inn[2][4];
#pragma unroll
        for (int fp = 0; fp < 2; fp++)
#pragma unroll
            for (int u = 0; u < 4; u++) acc_inn[fp][u] = 0.0f;

        // x(t) from SMEM stage: build x-fold A fragment (LDS only)
        const float* xb = (const float*)(smem + SW_XB) + par * 128;
        uint4 xfrag;
        {
            const int r0 = (L >> 2), c0 = (L & 3) << 1;
            float2 a = *(const float2*)(xb + r0 * 8 + c0);
            float2 b = *(const float2*)(xb + (r0 + 8) * 8 + c0);
            const unsigned one = ((L & 3) == 0) ? f2h2(1.0f, 0.0f) : 0u;
            xfrag.x = f2h2(a.x, a.y);
            xfrag.y = f2h2(b.x, b.y);
            xfrag.z = one;
            xfrag.w = one;
        }

        // warp 0: prefetch x(t+1) (covered by the whole MMA phase)
        float4 xnv = make_float4(0.f, 0.f, 0.f, 0.f);
        const bool pf = (tid < 32) && (t < Wlen - 1);
        if (pf) {
            const int prow = tid >> 1, phalf = tid & 1;
            xnv = __ldg((const float4*)(x + (size_t)(bcta * 16 + prow) * (Wlen * Fin)
                                          + (t + 1) * Fin + phalf * 4));
        }

        // issue ALL 4 initial streamed-B loads (chunks 7..10) up front
        uint2 Bs[4][6];
#pragma unroll
        for (int d = 0; d < 4; d++)
#pragma unroll
            for (int nf = 0; nf < 6; nf++)
                Bs[d][nf] = __ldcg((const uint2*)(gW + (7 + d) * 768 + nf * 64 + (L << 1)));

        // x-fold chunk (resident slot 7): r/z/hn gates, A in registers
        {
            const unsigned* bb = smem + resbase + 7 * 768 + (L << 1);
#pragma unroll
            for (int nf = 0; nf < 6; nf++) {
                uint2 bw = *(const uint2*)(bb + nf * 64);
                MMAH(acc[nf], xfrag, bw.x, bw.y);
            }
        }
        // inn-xfold: 2 MMAs into the separate accumulator (no h contributions)
#pragma unroll
        for (int fp = 0; fp < 2; fp++) {
            uint2 bw = *(const uint2*)(smem + fxbase + fp * 64);
            MMAH(acc_inn[fp], xfrag, bw.x, bw.y);
        }
        // resident h-chunks 0..6 (A from SMEM, B from SMEM)
#pragma unroll
        for (int q = 0; q < 7; q++) {
            uint4 af = *(const uint4*)(hsrc + q * 128 + (L << 2));
            const unsigned* bb = smem + resbase + q * 768 + (L << 1);
#pragma unroll
            for (int nf = 0; nf < 6; nf++) {
                uint2 bw = *(const uint2*)(bb + nf * 64);
                MMAH(acc[nf], af, bw.x, bw.y);
            }
        }
        // streamed h-chunks 7..15 (A from SMEM, B from depth-4 register ring)
#pragma unroll
        for (int d = 0; d < 9; d++) {
            const int q = 7 + d;
            const int s = d & 3;
            uint4 af = *(const uint4*)(hsrc + q * 128 + (L << 2));
#pragma unroll
            for (int nf = 0; nf < 6; nf++)
                MMAH(acc[nf], af, Bs[s][nf].x, Bs[s][nf].y);
            if (d + 4 < 9) {
#pragma unroll
                for (int nf = 0; nf < 6; nf++)
                    Bs[s][nf] = __ldcg((const uint2*)(gW + (q + 4) * 768 + nf * 64 + (L << 1)));
            }
        }

        // stage x(t+1) into the other xbuf (ordered by next step's sync)
        if (pf) {
            const int prow = tid >> 1, phalf = tid & 1;
            *(float4*)((float*)(smem + SW_XB) + (par ^ 1) * 128 + prow * 8 + phalf * 4) = xnv;
        }

        // ---- epilogue: MUFU.TANH gates + h update + STS (no inn chain) ----
        float hv[2][2][2];                 // [rh][fp][e]
#pragma unroll
        for (int fp = 0; fp < 2; fp++) {
#pragma unroll
            for (int e = 0; e < 2; e++) {
#pragma unroll
                for (int rh = 0; rh < 2; rh++) {
                    const int ci = rh * 2 + e;
                    float rp  = acc[fp][ci];          // bias+x folded via MMA
                    float zp  = acc[2 + fp][ci];
                    float hnv = acc[4 + fp][ci];      // includes bhn
                    float xn  = acc_inn[fp][ci];      // inn + bin via MMA
                    float r = fmaf(tanh_fast(0.5f * rp), 0.5f, 0.5f);
                    float z = fmaf(tanh_fast(0.5f * zp), 0.5f, 0.5f);
                    float an = fmaf(r, hnv, xn);
                    float n  = tanh_fast(an);         // saturates; no clamp
                    const int hidx = (rh * 2 + fp) * 2 + e;
                    float h = fmaf(z, hold[hidx] - n, n);   // (1-z)n + z*hold
                    hold[hidx] = h;
                    hv[rh][fp][e] = h;
                }
            }
        }
        unsigned whi[4];
#pragma unroll
        for (int rh = 0; rh < 2; rh++)
#pragma unroll
            for (int fp = 0; fp < 2; fp++)
                whi[rh + 2 * fp] = f2h2(hv[rh][fp][0], hv[rh][fp][1]);
        // warp w produces exactly chunk w
        *(uint4*)(hdst + w * 128 + (L << 2)) =
            make_uint4(whi[0], whi[1], whi[2], whi[3]);
    }

    // final h -> plain layout for the head
#pragma unroll
    for (int rh = 0; rh < 2; rh++) {
        const int row = bcta * 16 + (L >> 2) + 8 * rh;
#pragma unroll
        for (int fp = 0; fp < 2; fp++)
#pragma unroll
            for (int e = 0; e < 2; e++) {
                const int jl = wc * 16 + 2 * (L & 3) + 8 * fp + e;
                const int hidx = (rh * 2 + fp) * 2 + e;
                g_hfinal[(size_t)row * 256 + c * 32 + jl] = hold[hidx];
            }
    }
}

// ---------------- head: h_bwd + projection + GELU + LayerNorm ---------------
__global__ void __launch_bounds__(256)
head_kernel(const float* __restrict__ x,
            const float* __restrict__ Wih_b,
            const float* __restrict__ bih_b,
            const float* __restrict__ bhh_b,
            const float* __restrict__ bp,
            const float* __restrict__ gamma,
            const float* __restrict__ beta,
            float* __restrict__ out) {
    __shared__ float hf[8][Hdim];
    __shared__ float hb[8][Hdim];
    __shared__ float ys[8][Hdim];
    __shared__ float xs[8][Fin];

    const int tx = threadIdx.x;
    const int b0 = blockIdx.x * 8;

    for (int idx = tx; idx < 8 * Hdim; idx += 256) {
        int r = idx >> 8, k = idx & 255;
        hf[r][k] = g_hfinal[(size_t)(b0 + r) * Hdim + k];
    }
    if (tx < 64) {
        int r = tx >> 3, cc = tx & 7;
        xs[r][cc] = x[(size_t)(b0 + r) * (Wlen * Fin) + (Wlen - 1) * Fin + cc];
    }
    __syncthreads();

    {   // backward cell at h0 = 0 (exact math)
        const int j = tx;
        float wr[Fin], wz[Fin], wn[Fin];
#pragma unroll
        for (int cc = 0; cc < Fin; cc++) {
            wr[cc] = Wih_b[j * Fin + cc];
            wz[cc] = Wih_b[(256 + j) * Fin + cc];
            wn[cc] = Wih_b[(512 + j) * Fin + cc];
        }
        const float bir = bih_b[j],       bhr = bhh_b[j];
        const float biz = bih_b[256 + j], bhz = bhh_b[256 + j];
        const float bin = bih_b[512 + j], bhn = bhh_b[512 + j];
#pragma unroll
        for (int r8 = 0; r8 < 8; r8++) {
            float gr = bir + bhr, gz = biz + bhz, gn = bin;
#pragma unroll
            for (int cc = 0; cc < Fin; cc++) {
                float xvv = xs[r8][cc];
                gr = fmaf(xvv, wr[cc], gr);
                gz = fmaf(xvv, wz[cc], gz);
                gn = fmaf(xvv, wn[cc], gn);
            }
            float r = 1.0f / (1.0f + __expf(-gr));
            float z = 1.0f / (1.0f + __expf(-gz));
            float an = gn + r * bhn;
            an = fminf(fmaxf(an, -15.0f), 15.0f);
            float e = __expf(-2.0f * an);
            float n = (1.0f - e) / (1.0f + e);
            hb[r8][j] = (1.0f - z) * n;
        }
    }
    __syncthreads();

    {   // projection + exact GELU
        const int j = tx;
#pragma unroll
        for (int r8 = 0; r8 < 8; r8++) {
            float acc = bp[j];
#pragma unroll 4
            for (int k = 0; k < Hdim; k++)
                acc = fmaf(hf[r8][k], g_Wpt[k * Hdim + j], acc);
#pragma unroll 4
            for (int k = 0; k < Hdim; k++)
                acc = fmaf(hb[r8][k], g_Wpt[(Hdim + k) * Hdim + j], acc);
            ys[r8][j] = 0.5f * acc * (1.0f + erff(acc * 0.70710678118654752f));
        }
    }
    __syncthreads();

    const int w = tx >> 5, l = tx & 31;
    float s1 = 0.f, s2 = 0.f;
#pragma unroll
    for (int m = 0; m < 8; m++) {
        float v = ys[w][l + 32 * m];
        s1 += v; s2 += v * v;
    }
#pragma unroll
    for (int o = 16; o > 0; o >>= 1) {
        s1 += __shfl_xor_sync(0xffffffffu, s1, o);
        s2 += __shfl_xor_sync(0xffffffffu, s2, o);
    }
    const float mu  = s1 * (1.0f / 256.0f);
    const float var = s2 * (1.0f / 256.0f) - mu * mu;
    const float inv = rsqrtf(var + 1e-5f);
#pragma unroll
    for (int m = 0; m < 8; m++) {
        int col = l + 32 * m;
        float v = (ys[w][col] - mu) * inv;
        out[(size_t)(b0 + w) * Hdim + col] = v * gamma[col] + beta[col];
    }
}

// ---------------------------------------------------------------------------
extern "C" void kernel_launch(void* const* d_in, const int* in_sizes, int n_in,
                              void* d_out, int out_size) {
    const float* x     = (const float*)d_in[0];
    const float* Wih_f = (const float*)d_in[1];
    const float* Whh_f = (const float*)d_in[2];
    const float* bih_f = (const float*)d_in[3];
    const float* bhh_f = (const float*)d_in[4];
    const float* Wih_b = (const float*)d_in[5];
    /* Whh_b = d_in[6] unused: backward cell has h0 = 0 */
    const float* bih_b = (const float*)d_in[7];
    const float* bhh_b = (const float*)d_in[8];
    const float* Wp    = (const float*)d_in[9];
    const float* bp    = (const float*)d_in[10];
    const float* gamma = (const float*)d_in[11];
    const float* beta  = (const float*)d_in[12];
    float* out = (float*)d_out;

    cudaFuncSetAttribute(gru_persist, cudaFuncAttributeMaxDynamicSharedMemorySize, SM_TOTAL);

    prep_kernel<<<(N_PREP + 255) / 256, 256>>>(Whh_f, Wih_f, bih_f, bhh_f, Wp);
    gru_persist<<<Bsz / 16, THREADS, SM_TOTAL>>>(x);
    head_kernel<<<Bsz / 8, 256>>>(x, Wih_b, bih_b, bhh_b, bp, gamma, beta, out);
}